// round 5
// baseline (speedup 1.0000x reference)
#include <cuda_runtime.h>
#include <cstdint>

#define N_MAX 100000
#define E_MAX 1600000
#define IN_C 64
#define HID_C 64
#define OUT_C 32
#define FULL 0xffffffffu

// ---------------- scratch (no allocations allowed) ----------------
__device__ int   g_cnt[N_MAX];
__device__ int   g_cur[N_MAX];
__device__ int   g_off[N_MAX + 1];
__device__ int   g_adj[E_MAX];
__device__ int   g_bsum[128];
__device__ int   g_bpre[128];
__device__ int   g_mx;                     // encoded global max of a_s
__device__ __align__(16) float g_agg[N_MAX * IN_C];
__device__ __align__(16) float g_z[N_MAX * OUT_C];
__device__ float g_as[N_MAX];
__device__ float g_ad[N_MAX];

__device__ __forceinline__ float lrelu(float v) {
    return v > 0.0f ? v : 0.2f * v;
}
// order-preserving float<->int encoding for atomicMax
__device__ __forceinline__ int fenc(float f) {
    int b = __float_as_int(f);
    return (b >= 0) ? b : (b ^ 0x7fffffff);
}
__device__ __forceinline__ float fdec(int k) {
    return __int_as_float((k >= 0) ? k : (k ^ 0x7fffffff));
}

// packed f32x2 helpers (Blackwell)
__device__ __forceinline__ void fma2(unsigned long long& d,
                                     unsigned long long a,
                                     unsigned long long b) {
    asm("fma.rn.f32x2 %0, %1, %2, %0;" : "+l"(d) : "l"(a), "l"(b));
}
__device__ __forceinline__ unsigned long long pack2(float v) {
    unsigned long long r;
    asm("mov.b64 %0, {%1, %1};" : "=l"(r) : "f"(v));
    return r;
}
__device__ __forceinline__ unsigned long long packf(float a, float b) {
    unsigned long long r;
    asm("mov.b64 %0, {%1, %2};" : "=l"(r) : "f"(a), "f"(b));
    return r;
}
__device__ __forceinline__ float2 unpack2(unsigned long long v) {
    float2 f;
    asm("mov.b64 {%0, %1}, %2;" : "=f"(f.x), "=f"(f.y) : "l"(v));
    return f;
}

// ---------------- K1: histogram of dst (4 edges/thread, int4) ----------------
__global__ void k_hist(const int* __restrict__ dst, int E) {
    unsigned i = (blockIdx.x * blockDim.x + threadIdx.x) * 4u;
    if (i + 4 <= (unsigned)E) {
        int4 d = *reinterpret_cast<const int4*>(dst + i);
        atomicAdd(&g_cnt[d.x], 1);
        atomicAdd(&g_cnt[d.y], 1);
        atomicAdd(&g_cnt[d.z], 1);
        atomicAdd(&g_cnt[d.w], 1);
    } else {
        for (; i < (unsigned)E; i++) atomicAdd(&g_cnt[dst[i]], 1);
    }
}

// ---------------- K2: hierarchical exclusive scan ----------------
__global__ void k_scan_local(int n) {
    __shared__ int wsum[32];
    int b = blockIdx.x, t = threadIdx.x;
    int i = b * 1024 + t;
    int v = (i < n) ? g_cnt[i] : 0;
    int orig = v;
    int lane = t & 31, w = t >> 5;
#pragma unroll
    for (int o = 1; o < 32; o <<= 1) {
        int u = __shfl_up_sync(FULL, v, o);
        if (lane >= o) v += u;
    }
    if (lane == 31) wsum[w] = v;
    __syncthreads();
    if (w == 0) {
        int s = wsum[lane];
#pragma unroll
        for (int o = 1; o < 32; o <<= 1) {
            int u = __shfl_up_sync(FULL, s, o);
            if (lane >= o) s += u;
        }
        wsum[lane] = s;
    }
    __syncthreads();
    int excl = v - orig + (w > 0 ? wsum[w - 1] : 0);
    if (i < n) g_off[i] = excl;
    if (t == 1023) g_bsum[b] = wsum[31];
}

__global__ void k_scan_bsums(int nb, int n) {
    __shared__ int tmp[128];
    int t = threadIdx.x;
    if (t == 0) g_mx = 0x80000000;      // init global a_s max (INT_MIN)
    int v = (t < nb) ? g_bsum[t] : 0;
    tmp[t] = v;
    __syncthreads();
    for (int o = 1; o < 128; o <<= 1) {
        int u = (t >= o) ? tmp[t - o] : 0;
        __syncthreads();
        tmp[t] += u;
        __syncthreads();
    }
    if (t < nb) g_bpre[t] = tmp[t] - v;
    if (t == nb - 1) g_off[n] = tmp[t];
}

__global__ void k_scan_add(int n) {
    int b = blockIdx.x;
    int i = b * 1024 + threadIdx.x;
    if (i < n && b > 0) g_off[i] += g_bpre[b];
}

// ---------------- K3: fill adjacency (4 edges/thread) ----------------
__global__ void k_fill(const int* __restrict__ src,
                       const int* __restrict__ dst,
                       int E) {
    unsigned i = (blockIdx.x * blockDim.x + threadIdx.x) * 4u;
    if (i + 4 <= (unsigned)E) {
        int4 d = *reinterpret_cast<const int4*>(dst + i);
        int4 s = *reinterpret_cast<const int4*>(src + i);
        g_adj[g_off[d.x] + atomicAdd(&g_cur[d.x], 1)] = s.x;
        g_adj[g_off[d.y] + atomicAdd(&g_cur[d.y], 1)] = s.y;
        g_adj[g_off[d.z] + atomicAdd(&g_cur[d.z], 1)] = s.z;
        g_adj[g_off[d.w] + atomicAdd(&g_cur[d.w], 1)] = s.w;
    } else {
        for (; i < (unsigned)E; i++) {
            int d = dst[i];
            g_adj[g_off[d] + atomicAdd(&g_cur[d], 1)] = src[i];
        }
    }
}

// ---------------- K4a: mean aggregation (vectorized gather) ----------------
__global__ void k_agg(const float* __restrict__ x, int n) {
    int node = (blockIdx.x * blockDim.x + threadIdx.x) >> 5;
    int lane = threadIdx.x & 31;
    if (node >= n) return;
    int beg = g_off[node];
    int end = g_off[node + 1];
    int half = lane >> 4;
    int q = lane & 15;

    float4 acc0 = make_float4(0.f, 0.f, 0.f, 0.f);
    float4 acc1 = make_float4(0.f, 0.f, 0.f, 0.f);
    int j = beg;
    for (; j + 4 <= end; j += 4) {
        int s0 = g_adj[j + half];
        int s1 = g_adj[j + 2 + half];
        float4 v0 = *reinterpret_cast<const float4*>(x + (size_t)s0 * IN_C + q * 4);
        float4 v1 = *reinterpret_cast<const float4*>(x + (size_t)s1 * IN_C + q * 4);
        acc0.x += v0.x; acc0.y += v0.y; acc0.z += v0.z; acc0.w += v0.w;
        acc1.x += v1.x; acc1.y += v1.y; acc1.z += v1.z; acc1.w += v1.w;
    }
    for (; j + 2 <= end; j += 2) {
        int s = g_adj[j + half];
        float4 v = *reinterpret_cast<const float4*>(x + (size_t)s * IN_C + q * 4);
        acc0.x += v.x; acc0.y += v.y; acc0.z += v.z; acc0.w += v.w;
    }
    if (j < end && half == 0) {
        int s = g_adj[j];
        float4 v = *reinterpret_cast<const float4*>(x + (size_t)s * IN_C + q * 4);
        acc0.x += v.x; acc0.y += v.y; acc0.z += v.z; acc0.w += v.w;
    }
    acc0.x += acc1.x; acc0.y += acc1.y; acc0.z += acc1.z; acc0.w += acc1.w;
    acc0.x += __shfl_down_sync(FULL, acc0.x, 16);
    acc0.y += __shfl_down_sync(FULL, acc0.y, 16);
    acc0.z += __shfl_down_sync(FULL, acc0.z, 16);
    acc0.w += __shfl_down_sync(FULL, acc0.w, 16);

    float inv = 1.0f / fmaxf((float)(end - beg), 1.0f);
    if (lane < 16) {
        float4 r = make_float4(acc0.x * inv, acc0.y * inv, acc0.z * inv, acc0.w * inv);
        *reinterpret_cast<float4*>(g_agg + (size_t)node * IN_C + q * 4) = r;
    }
}

// ---------------- K4b: register-tiled node forward GEMM ----------------
__global__ void __launch_bounds__(128) k_forward(
        const float* __restrict__ x,
        const float* __restrict__ W_l,
        const float* __restrict__ W_r,
        const float* __restrict__ b1,
        const float* __restrict__ W_g,
        const float* __restrict__ att_src,
        const float* __restrict__ att_dst,
        int n) {
    extern __shared__ float sm[];
    float* sIn = sm;                 // [128][64] (k-major); reused as sH
    float* sW  = sm + 128 * 64;      // [128][64]; reused as att partials
    float* sWg = sm + 2 * 128 * 64;  // [64][32]

    int tid = threadIdx.x;
    int node0 = blockIdx.x * 64;

    for (int i = tid; i < 2048; i += 128) {
        int k = i >> 4, q = i & 15;
        const float* sp = (k < 64) ? (W_l + k * 64 + q * 4)
                                   : (W_r + (k - 64) * 64 + q * 4);
        *reinterpret_cast<float4*>(&sW[k * 64 + q * 4]) =
            *reinterpret_cast<const float4*>(sp);
    }
    for (int i = tid; i < 512; i += 128) {
        int k = i >> 3, q = i & 7;
        *reinterpret_cast<float4*>(&sWg[k * 32 + q * 4]) =
            *reinterpret_cast<const float4*>(W_g + k * 32 + q * 4);
    }
    for (int i = tid; i < 1024; i += 128) {
        int node = i & 63, q = i >> 6;
        int gnode = node0 + node;
        float4 va = make_float4(0.f, 0.f, 0.f, 0.f);
        float4 vx = make_float4(0.f, 0.f, 0.f, 0.f);
        if (gnode < n) {
            va = *reinterpret_cast<const float4*>(g_agg + (size_t)gnode * IN_C + q * 4);
            vx = *reinterpret_cast<const float4*>(x + (size_t)gnode * IN_C + q * 4);
        }
        int kb = q * 4;
        sIn[(kb + 0) * 64 + node] = va.x;
        sIn[(kb + 1) * 64 + node] = va.y;
        sIn[(kb + 2) * 64 + node] = va.z;
        sIn[(kb + 3) * 64 + node] = va.w;
        sIn[(kb + 64) * 64 + node] = vx.x;
        sIn[(kb + 65) * 64 + node] = vx.y;
        sIn[(kb + 66) * 64 + node] = vx.z;
        sIn[(kb + 67) * 64 + node] = vx.w;
    }
    __syncthreads();

    int ng = tid & 7;
    int cg = tid >> 3;
    int ngb = ng * 8;
    int cb = cg * 4;

    unsigned long long acc[4][4];
#pragma unroll
    for (int j = 0; j < 4; j++)
#pragma unroll
        for (int p = 0; p < 4; p++) acc[j][p] = 0ull;

#pragma unroll 2
    for (int k = 0; k < 128; k++) {
        ulonglong2 inA = *reinterpret_cast<const ulonglong2*>(&sIn[k * 64 + ngb]);
        ulonglong2 inB = *reinterpret_cast<const ulonglong2*>(&sIn[k * 64 + ngb + 4]);
        float4 w = *reinterpret_cast<const float4*>(&sW[k * 64 + cb]);
        unsigned long long w0 = pack2(w.x), w1 = pack2(w.y);
        unsigned long long w2 = pack2(w.z), w3 = pack2(w.w);
        fma2(acc[0][0], inA.x, w0); fma2(acc[0][1], inA.y, w0);
        fma2(acc[0][2], inB.x, w0); fma2(acc[0][3], inB.y, w0);
        fma2(acc[1][0], inA.x, w1); fma2(acc[1][1], inA.y, w1);
        fma2(acc[1][2], inB.x, w1); fma2(acc[1][3], inB.y, w1);
        fma2(acc[2][0], inA.x, w2); fma2(acc[2][1], inA.y, w2);
        fma2(acc[2][2], inB.x, w2); fma2(acc[2][3], inB.y, w2);
        fma2(acc[3][0], inA.x, w3); fma2(acc[3][1], inA.y, w3);
        fma2(acc[3][2], inB.x, w3); fma2(acc[3][3], inB.y, w3);
    }
    __syncthreads();

    float* sH = sIn;
    float b1v0 = b1[cb], b1v1 = b1[cb + 1], b1v2 = b1[cb + 2], b1v3 = b1[cb + 3];
#pragma unroll
    for (int p = 0; p < 4; p++) {
        float2 v0 = unpack2(acc[0][p]);
        float2 v1 = unpack2(acc[1][p]);
        float2 v2 = unpack2(acc[2][p]);
        float2 v3 = unpack2(acc[3][p]);
        int nb_ = ngb + 2 * p;
        *reinterpret_cast<unsigned long long*>(&sH[(cb + 0) * 64 + nb_]) =
            packf(fmaxf(v0.x + b1v0, 0.f), fmaxf(v0.y + b1v0, 0.f));
        *reinterpret_cast<unsigned long long*>(&sH[(cb + 1) * 64 + nb_]) =
            packf(fmaxf(v1.x + b1v1, 0.f), fmaxf(v1.y + b1v1, 0.f));
        *reinterpret_cast<unsigned long long*>(&sH[(cb + 2) * 64 + nb_]) =
            packf(fmaxf(v2.x + b1v2, 0.f), fmaxf(v2.y + b1v2, 0.f));
        *reinterpret_cast<unsigned long long*>(&sH[(cb + 3) * 64 + nb_]) =
            packf(fmaxf(v3.x + b1v3, 0.f), fmaxf(v3.y + b1v3, 0.f));
    }
    __syncthreads();

    int c2 = cg * 2;
    unsigned long long z0[4], z1[4];
#pragma unroll
    for (int p = 0; p < 4; p++) { z0[p] = 0ull; z1[p] = 0ull; }

#pragma unroll 2
    for (int k = 0; k < 64; k++) {
        ulonglong2 inA = *reinterpret_cast<const ulonglong2*>(&sH[k * 64 + ngb]);
        ulonglong2 inB = *reinterpret_cast<const ulonglong2*>(&sH[k * 64 + ngb + 4]);
        float2 w = *reinterpret_cast<const float2*>(&sWg[k * 32 + c2]);
        unsigned long long w0 = pack2(w.x), w1 = pack2(w.y);
        fma2(z0[0], inA.x, w0); fma2(z0[1], inA.y, w0);
        fma2(z0[2], inB.x, w0); fma2(z0[3], inB.y, w0);
        fma2(z1[0], inA.x, w1); fma2(z1[1], inA.y, w1);
        fma2(z1[2], inB.x, w1); fma2(z1[3], inB.y, w1);
    }

    float asc0 = att_src[c2], asc1 = att_src[c2 + 1];
    float adc0 = att_dst[c2], adc1 = att_dst[c2 + 1];
    float* sAsP = sW;
    float* sAdP = sW + 16 * 64;

#pragma unroll
    for (int p = 0; p < 4; p++) {
        float2 za = unpack2(z0[p]);
        float2 zb = unpack2(z1[p]);
        int nA = ngb + 2 * p;
        int gA = node0 + nA;
        if (gA < n)
            *reinterpret_cast<float2*>(g_z + (size_t)gA * OUT_C + c2) =
                make_float2(za.x, zb.x);
        if (gA + 1 < n)
            *reinterpret_cast<float2*>(g_z + (size_t)(gA + 1) * OUT_C + c2) =
                make_float2(za.y, zb.y);
        sAsP[cg * 64 + nA]     = za.x * asc0 + zb.x * asc1;
        sAsP[cg * 64 + nA + 1] = za.y * asc0 + zb.y * asc1;
        sAdP[cg * 64 + nA]     = za.x * adc0 + zb.x * adc1;
        sAdP[cg * 64 + nA + 1] = za.y * adc0 + zb.y * adc1;
    }
    __syncthreads();

    // reduce att partials; track block max of a_s for the global softmax bound
    float samax = -3.4e38f;
    if (tid < 64) {
        int g = node0 + tid;
        if (g < n) {
            float sa = 0.f, sd = 0.f;
#pragma unroll
            for (int c = 0; c < 16; c++) {
                sa += sAsP[c * 64 + tid];
                sd += sAdP[c * 64 + tid];
            }
            g_as[g] = sa;
            g_ad[g] = sd;
            samax = sa;
        }
#pragma unroll
        for (int o = 16; o > 0; o >>= 1)
            samax = fmaxf(samax, __shfl_xor_sync(FULL, samax, o));
        if ((tid & 31) == 0) sWg[tid >> 5] = samax;
    }
    __syncthreads();
    if (tid == 0) atomicMax(&g_mx, fenc(fmaxf(sWg[0], sWg[1])));
}

// ---------------- K5: GAT, single pass (global upper-bound shift) ----------------
// one warp per dst node; 32 lanes = 4 neighbor-groups x 8 float4 chunks
__global__ void k_gat(const float* __restrict__ b2,
                      float* __restrict__ out,
                      int n) {
    int node = (blockIdx.x * blockDim.x + threadIdx.x) >> 5;
    int lane = threadIdx.x & 31;
    if (node >= n) return;
    int beg = g_off[node];
    int end = g_off[node + 1];
    int grp = lane >> 3;
    int q = lane & 7;

    float ad_ = g_ad[node];
    // shift by per-dst upper bound: lrelu monotone => e <= lrelu(gmax_as + ad)
    float M = lrelu(fdec(g_mx) + ad_);

    float sumA = 0.0f, sumB = 0.0f;
    float4 accA = make_float4(0.f, 0.f, 0.f, 0.f);
    float4 accB = make_float4(0.f, 0.f, 0.f, 0.f);
    if (grp == 0) {
        float w = __expf(lrelu(g_as[node] + ad_) - M);
        sumA = w;
        float4 zv = *reinterpret_cast<const float4*>(g_z + (size_t)node * OUT_C + q * 4);
        accA = make_float4(w * zv.x, w * zv.y, w * zv.z, w * zv.w);
    }
    int j = beg + grp;
    for (; j + 4 < end; j += 8) {
        int s0 = g_adj[j];
        int s1 = g_adj[j + 4];
        float w0 = __expf(lrelu(g_as[s0] + ad_) - M);
        float w1 = __expf(lrelu(g_as[s1] + ad_) - M);
        float4 zv0 = *reinterpret_cast<const float4*>(g_z + (size_t)s0 * OUT_C + q * 4);
        float4 zv1 = *reinterpret_cast<const float4*>(g_z + (size_t)s1 * OUT_C + q * 4);
        sumA += w0; sumB += w1;
        accA.x = fmaf(w0, zv0.x, accA.x); accB.x = fmaf(w1, zv1.x, accB.x);
        accA.y = fmaf(w0, zv0.y, accA.y); accB.y = fmaf(w1, zv1.y, accB.y);
        accA.z = fmaf(w0, zv0.z, accA.z); accB.z = fmaf(w1, zv1.z, accB.z);
        accA.w = fmaf(w0, zv0.w, accA.w); accB.w = fmaf(w1, zv1.w, accB.w);
    }
    if (j < end) {
        int s = g_adj[j];
        float w = __expf(lrelu(g_as[s] + ad_) - M);
        float4 zv = *reinterpret_cast<const float4*>(g_z + (size_t)s * OUT_C + q * 4);
        sumA += w;
        accA.x = fmaf(w, zv.x, accA.x);
        accA.y = fmaf(w, zv.y, accA.y);
        accA.z = fmaf(w, zv.z, accA.z);
        accA.w = fmaf(w, zv.w, accA.w);
    }
    float sum = sumA + sumB;
    float4 acc = make_float4(accA.x + accB.x, accA.y + accB.y,
                             accA.z + accB.z, accA.w + accB.w);

    sum += __shfl_xor_sync(FULL, sum, 8);
    sum += __shfl_xor_sync(FULL, sum, 16);
    acc.x += __shfl_xor_sync(FULL, acc.x, 8);  acc.x += __shfl_xor_sync(FULL, acc.x, 16);
    acc.y += __shfl_xor_sync(FULL, acc.y, 8);  acc.y += __shfl_xor_sync(FULL, acc.y, 16);
    acc.z += __shfl_xor_sync(FULL, acc.z, 8);  acc.z += __shfl_xor_sync(FULL, acc.z, 16);
    acc.w += __shfl_xor_sync(FULL, acc.w, 8);  acc.w += __shfl_xor_sync(FULL, acc.w, 16);

    float inv = 1.0f / sum;
    float4 o4;
    o4.x = acc.x * inv + b2[q * 4 + 0];
    o4.y = acc.y * inv + b2[q * 4 + 1];
    o4.z = acc.z * inv + b2[q * 4 + 2];
    o4.w = acc.w * inv + b2[q * 4 + 3];

    float mx = fmaxf(fmaxf(o4.x, o4.y), fmaxf(o4.z, o4.w));
#pragma unroll
    for (int off = 1; off < 8; off <<= 1)
        mx = fmaxf(mx, __shfl_xor_sync(FULL, mx, off));
    float se = __expf(o4.x - mx) + __expf(o4.y - mx) + __expf(o4.z - mx) + __expf(o4.w - mx);
#pragma unroll
    for (int off = 1; off < 8; off <<= 1)
        se += __shfl_xor_sync(FULL, se, off);
    float ls = mx + logf(se);

    if (lane < 8) {
        float4 r = make_float4(o4.x - ls, o4.y - ls, o4.z - ls, o4.w - ls);
        *reinterpret_cast<float4*>(out + (size_t)node * OUT_C + q * 4) = r;
    }
}

// ---------------- launch ----------------
extern "C" void kernel_launch(void* const* d_in, const int* in_sizes, int n_in,
                              void* d_out, int out_size) {
    const float* x       = (const float*)d_in[0];
    const int*   ei      = (const int*)d_in[1];
    const float* W_l     = (const float*)d_in[2];
    const float* W_r     = (const float*)d_in[3];
    const float* b1      = (const float*)d_in[4];
    const float* W_g     = (const float*)d_in[5];
    const float* att_src = (const float*)d_in[6];
    const float* att_dst = (const float*)d_in[7];
    const float* b2      = (const float*)d_in[8];
    float* out = (float*)d_out;

    int N = in_sizes[0] / IN_C;
    int E = in_sizes[1] / 2;
    const int* src = ei;
    const int* dst = ei + E;

    void *p_cnt, *p_cur;
    cudaGetSymbolAddress(&p_cnt, g_cnt);
    cudaGetSymbolAddress(&p_cur, g_cur);
    cudaMemsetAsync(p_cnt, 0, (size_t)N * sizeof(int), 0);
    cudaMemsetAsync(p_cur, 0, (size_t)N * sizeof(int), 0);

    int nb_scan = (N + 1023) / 1024;
    unsigned e4 = ((unsigned)E + 3u) / 4u;
    k_hist<<<(e4 + 255u) / 256u, 256>>>(dst, E);
    k_scan_local<<<nb_scan, 1024>>>(N);
    k_scan_bsums<<<1, 128>>>(nb_scan, N);
    k_scan_add<<<nb_scan, 1024>>>(N);
    k_fill<<<(e4 + 255u) / 256u, 256>>>(src, dst, E);

    k_agg<<<(N + 7) / 8, 256>>>(x, N);

    size_t smemF = (size_t)(128 * 64 + 128 * 64 + 64 * 32) * sizeof(float);
    cudaFuncSetAttribute(k_forward, cudaFuncAttributeMaxDynamicSharedMemorySize,
                         (int)smemF);
    k_forward<<<(N + 63) / 64, 128, smemF>>>(x, W_l, W_r, b1, W_g,
                                             att_src, att_dst, N);

    k_gat<<<(N + 7) / 8, 256>>>(b2, out, N);
}